// round 14
// baseline (speedup 1.0000x reference)
#include <cuda_runtime.h>
#include <cuda_bf16.h>
#include <math.h>

#define BATCH 2
#define DIM   256
#define NC    19
#define TOPK  256
#define HF    128
#define WF    128
#define HH    512
#define WW    512
#define SPIX  (HF*WF)            // 16384
#define NPIX  (BATCH*HH*WW)      // 524288
#define EPSV  1e-12f
#define GAMMA_MAX 0.999f
#define NB    4096               // histogram bins over w in [0,1)
#define CCAP  1024               // candidate capacity (threshold bin)
#define GPARTS 8                 // gather blocks per class

#define WT_BLOCKS (NPIX / 256)   // 2048
#define TR_STILES (SPIX / 128)   // 128
#define TR_DTILES (DIM / 32)     // 8
#define TR_BLOCKS (BATCH * TR_STILES * TR_DTILES)  // 2048
#define SEL_BASE  (WT_BLOCKS + TR_BLOCKS)          // 4096
#define GA_BASE   (SEL_BASE + NC)                  // 4115
#define ALL_BLOCKS (GA_BASE + NC * GPARTS)         // 4267

// ---------------- scratch (static device memory; zero-init at load) ----------------
__device__ __align__(16) float g_fT[(size_t)BATCH*SPIX*DIM]; // features [B, HF*WF, DIM]
__device__ __align__(16) float g_cw[(size_t)NC*NPIX];        // per-class weight lists
__device__ __align__(16) int   g_cidx[(size_t)NC*NPIX];      // per-class pixel-index lists
__device__ __align__(16) int   g_hist[NC*NB];                // per-class global histograms
__device__ int   g_cnt[NC];                      // per-class list counts
__device__ float g_selw[NC*TOPK];                // selected weights
__device__ int   g_seli[NC*TOPK];                // selected pixel indices
__device__ float g_wsum[NC];                     // selected weight sums
__device__ int   g_has[NC];                      // class-present flags
__device__ int   g_ready[NC];                    // select->gather flags
__device__ __align__(16) float g_part[NC*GPARTS*DIM]; // gather partials
__device__ unsigned g_done[NC];                  // per-class gather tickets
__device__ unsigned g_gdone;                     // global gather ticket
__device__ unsigned g_wtdone;                    // weight-role completion counter
__device__ unsigned g_trdone;                    // transpose-role completion counter

// ---------------- helpers ----------------
__device__ __forceinline__ void src_coord(int o, int &i0, int &i1, float &f) {
    float s = (o + 0.5f) * 0.25f - 0.5f;
    float fl = floorf(s);
    f = s - fl;
    int i = (int)fl;
    i0 = min(max(i, 0), HF - 1);
    i1 = min(max(i + 1, 0), HF - 1);
}

__device__ __forceinline__ int w_bin(float w) {
    int b = (int)(w * (float)NB);
    return min(NB - 1, max(0, b));
}

// ================= single fused kernel: 4 roles, gate-synchronized =================
__global__ void __launch_bounds__(256) k_all(
        const float* __restrict__ f,
        const float* __restrict__ weight,
        const int* __restrict__ labels,
        const float* __restrict__ prototypes,
        const float* __restrict__ update_count,
        float* __restrict__ out, int out_size) {
    __shared__ __align__(16) char sbuf[16896];
    __shared__ int s_nsel, s_ncand, s_tb, s_last;
    int bid = blockIdx.x;
    int t = threadIdx.x;

    if (bid < WT_BLOCKS) {
        // ============ ROLE 1: per-pixel weight + list append + histogram ============
        int* s_cnt  = (int*)sbuf;             // [0,128)
        int* s_base = (int*)(sbuf + 128);     // [128,256)
        int n = bid * 256 + t;
        if (t < NC) s_cnt[t] = 0;
        __syncthreads();

        int lab = labels[n];
        bool valid = ((unsigned)lab < NC);
        float w = 0.f;
        int r = 0;
        if (valid) {
            int b   = n >> 18;
            int rem = n & (HH * WW - 1);
            int Y = rem >> 9;
            int X = rem & 511;
            int y0, y1, x0, x1; float fy, fx;
            src_coord(Y, y0, y1, fy);
            src_coord(X, x0, x1, fx);
            const float* wp = weight + ((size_t)(b * NC + lab)) * SPIX;
            float v00 = __ldg(wp + y0 * WF + x0);
            float v01 = __ldg(wp + y0 * WF + x1);
            float v10 = __ldg(wp + y1 * WF + x0);
            float v11 = __ldg(wp + y1 * WF + x1);
            w = (1.f - fy) * ((1.f - fx) * v00 + fx * v01)
              +        fy  * ((1.f - fx) * v10 + fx * v11);
            r = atomicAdd(&s_cnt[lab], 1);
            atomicAdd(&g_hist[lab * NB + w_bin(w)], 1);
        }
        __syncthreads();
        if (t < NC && s_cnt[t] > 0)
            s_base[t] = atomicAdd(&g_cnt[t], s_cnt[t]);
        __syncthreads();
        if (valid) {
            size_t o = (size_t)lab * NPIX + (size_t)(s_base[lab] + r);
            g_cw[o]   = w;
            g_cidx[o] = n;
        }
        __threadfence();
        __syncthreads();
        if (t == 0) atomicAdd(&g_wtdone, 1u);
        return;
    }

    if (bid < SEL_BASE) {
        // ============ ROLE 2: NCHW -> NHWC transpose (reg micro-transpose + swizzle) ============
        float4* tile4 = (float4*)sbuf;        // 16 KB: [128 s][8 col4]
        int i = bid - WT_BLOCKS;
        int s0 = (i & (TR_STILES - 1)) * 128;
        int d0 = ((i / TR_STILES) & (TR_DTILES - 1)) * 32;
        int b  = i / (TR_STILES * TR_DTILES);

        int dq = t >> 5;              // 0..7 : 4-dim group
        int sq = t & 31;              // 0..31: 4-spatial group
        float4 v0 = __ldg((const float4*)(f + ((size_t)(b * DIM + d0 + 4 * dq + 0)) * SPIX + s0) + sq);
        float4 v1 = __ldg((const float4*)(f + ((size_t)(b * DIM + d0 + 4 * dq + 1)) * SPIX + s0) + sq);
        float4 v2 = __ldg((const float4*)(f + ((size_t)(b * DIM + d0 + 4 * dq + 2)) * SPIX + s0) + sq);
        float4 v3 = __ldg((const float4*)(f + ((size_t)(b * DIM + d0 + 4 * dq + 3)) * SPIX + s0) + sq);
        int col4 = dq ^ (sq & 7);
        tile4[(4 * sq + 0) * 8 + col4] = make_float4(v0.x, v1.x, v2.x, v3.x);
        tile4[(4 * sq + 1) * 8 + col4] = make_float4(v0.y, v1.y, v2.y, v3.y);
        tile4[(4 * sq + 2) * 8 + col4] = make_float4(v0.z, v1.z, v2.z, v3.z);
        tile4[(4 * sq + 3) * 8 + col4] = make_float4(v0.w, v1.w, v2.w, v3.w);
        __syncthreads();

        int d4 = t & 7;
        int sl = t >> 3;
        #pragma unroll
        for (int q = 0; q < 4; q++) {
            int s = sl + 32 * q;
            float4 v = tile4[s * 8 + (d4 ^ ((s >> 2) & 7))];
            *((float4*)(g_fT + ((size_t)(b * SPIX + s0 + s)) * DIM + d0) + d4) = v;
        }
        __threadfence();
        __syncthreads();
        if (t == 0) atomicAdd(&g_trdone, 1u);
        return;
    }

    if (bid < GA_BASE) {
        // ============ ROLE 3: per-class top-256 select (gated on weight completion) ============
        int c = bid - SEL_BASE;
        int lane = t & 31, wid = t >> 5;
        float* s_w  = (float*)sbuf;               // 1 KB
        int*   s_i  = (int*)(sbuf + 1024);        // 1 KB
        float* s_cw = (float*)(sbuf + 2048);      // 4 KB
        int*   s_ci = (int*)(sbuf + 6144);        // 4 KB
        float* red  = (float*)(sbuf + 10240);     // 1 KB
        int*   wsc  = (int*)(sbuf + 11264);       // 32 B

        if (t == 0) {
            while (atomicAdd(&g_wtdone, 0u) < (unsigned)WT_BLOCKS) __nanosleep(128);
        }
        __syncthreads();
        __threadfence();

        int L = g_cnt[c];
        const float* cw = g_cw   + (size_t)c * NPIX;
        const int*   ci = g_cidx + (size_t)c * NPIX;

        // load my 16 histogram bins (descending chunks) + zero for next replay
        int4* hb = (int4*)(g_hist + c * NB);
        int base4 = (NB / 4) - 4 * (t + 1);       // 4 int4 = 16 bins per thread
        int4 q0 = hb[base4 + 0], q1 = hb[base4 + 1], q2 = hb[base4 + 2], q3 = hb[base4 + 3];
        int4 z = make_int4(0, 0, 0, 0);
        hb[base4 + 0] = z; hb[base4 + 1] = z; hb[base4 + 2] = z; hb[base4 + 3] = z;
        int cnts[16] = {q0.x, q0.y, q0.z, q0.w, q1.x, q1.y, q1.z, q1.w,
                        q2.x, q2.y, q2.z, q2.w, q3.x, q3.y, q3.z, q3.w};

        if (t == 0) { s_nsel = 0; s_ncand = 0; s_tb = -1; }
        __syncthreads();

        if (L <= TOPK) {
            for (int i = t; i < TOPK; i += 256) {
                if (i < L) { s_w[i] = cw[i]; s_i[i] = ci[i]; }
                else       { s_w[i] = 0.f;   s_i[i] = 0; }
            }
            __syncthreads();
        } else {
            // threshold bin via shuffle scan over 256 descending 16-bin chunks
            int chunk = 0;
            #pragma unroll
            for (int k = 0; k < 16; k++) chunk += cnts[k];
            int v = chunk;
            #pragma unroll
            for (int off = 1; off < 32; off <<= 1) {
                int nv = __shfl_up_sync(0xFFFFFFFFu, v, off);
                if (lane >= off) v += nv;
            }
            if (lane == 31) wsc[wid] = v;
            __syncthreads();
            if (wid == 0 && lane < 8) {
                int ws = wsc[lane];
                int vv = ws;
                #pragma unroll
                for (int off = 1; off < 8; off <<= 1) {
                    int nv = __shfl_up_sync(0xFFu, vv, off);
                    if (lane >= off) vv += nv;
                }
                wsc[lane] = vv - ws;       // exclusive warp offset
            }
            __syncthreads();
            int P_incl = v + wsc[wid];
            int P_excl = P_incl - chunk;
            if (P_incl >= TOPK && P_excl < TOPK) {
                int acc = P_excl;
                #pragma unroll
                for (int k = 15; k >= 0; k--) {
                    int h = cnts[k];
                    if (acc + h >= TOPK) { s_tb = 4 * base4 + k; break; }
                    acc += h;
                }
            }
            __syncthreads();
            int tb = s_tb;

            // single list pass: partition into selected / candidates
            int L4 = L & ~3;
            for (int i = t * 4; i < L4; i += 1024) {
                float4 vq = *(const float4*)(cw + i);
                int4   xq = *(const int4*)(ci + i);
                float wq[4] = {vq.x, vq.y, vq.z, vq.w};
                int   iq[4] = {xq.x, xq.y, xq.z, xq.w};
                #pragma unroll
                for (int j = 0; j < 4; j++) {
                    int bin = w_bin(wq[j]);
                    if (bin > tb) {
                        int p = atomicAdd(&s_nsel, 1);
                        s_w[p] = wq[j]; s_i[p] = iq[j];
                    } else if (bin == tb) {
                        int q = atomicAdd(&s_ncand, 1);
                        if (q < CCAP) { s_cw[q] = wq[j]; s_ci[q] = iq[j]; }
                    }
                }
            }
            for (int i = L4 + t; i < L; i += 256) {
                float w = cw[i];
                int bin = w_bin(w);
                if (bin > tb) {
                    int p = atomicAdd(&s_nsel, 1);
                    s_w[p] = w; s_i[p] = ci[i];
                } else if (bin == tb) {
                    int q = atomicAdd(&s_ncand, 1);
                    if (q < CCAP) { s_cw[q] = w; s_ci[q] = ci[i]; }
                }
            }
            __syncthreads();

            // parallel rank select from threshold bin
            int above = s_nsel;
            int r = TOPK - above;
            int L2 = min(s_ncand, CCAP);
            if (r > 0) {
                for (int i = t; i < L2; i += 256) {
                    float wi = s_cw[i];
                    int rank = 0;
                    for (int j = 0; j < L2; j++) {
                        float wj = s_cw[j];
                        rank += (wj > wi) || (wj == wi && j < i);
                    }
                    if (rank < r) { s_w[above + rank] = wi; s_i[above + rank] = s_ci[i]; }
                }
            }
            int nsel = above + ((r > 0) ? min(r, L2) : 0);
            __syncthreads();
            for (int i = t; i < TOPK; i += 256)
                if (i >= nsel) { s_w[i] = 0.f; s_i[i] = 0; }
            __syncthreads();
        }

        // weight sum + publish selection
        red[t] = s_w[t];
        g_selw[c * TOPK + t] = s_w[t];
        g_seli[c * TOPK + t] = s_i[t];
        __syncthreads();
        if (t < 128) red[t] += red[t + 128];
        __syncthreads();
        if (t < 64) red[t] += red[t + 64];
        __syncthreads();
        if (t < 32) {
            float v2 = red[t] + red[t + 32];
            #pragma unroll
            for (int off = 16; off > 0; off >>= 1)
                v2 += __shfl_down_sync(0xFFFFFFFFu, v2, off);
            if (t == 0) {
                g_wsum[c] = v2;
                g_has[c]  = (L > 0) && (v2 > 0.f);
                g_cnt[c]  = 0;             // cleanup for next graph replay
            }
        }
        __threadfence();
        __syncthreads();
        if (t == 0) atomicExch(&g_ready[c], 1);
        return;
    }

    // ============ ROLE 4: gather (gated on select[c] + transpose completion) ============
    {
        int g = bid - GA_BASE;
        int c = g >> 3;
        int p = g & (GPARTS - 1);
        int d4  = t & 63;
        int sub = t >> 6;

        float4* sv  = (float4*)sbuf;              // 4 KB
        float*  red = (float*)(sbuf + 4096);      // 1 KB

        if (t == 0) {
            while (atomicAdd(&g_ready[c], 0) == 0 ||
                   atomicAdd(&g_trdone, 0u) < (unsigned)TR_BLOCKS) __nanosleep(128);
        }
        __syncthreads();
        __threadfence();

        float4 acc = make_float4(0.f, 0.f, 0.f, 0.f);
        int k0 = p * 32 + sub * 8;
        #pragma unroll
        for (int k = k0; k < k0 + 8; k++) {
            float w = g_selw[c * TOPK + k];
            if (w > 0.f) {
                int n   = g_seli[c * TOPK + k];
                int b   = n >> 18;
                int rem = n & (HH * WW - 1);
                int Y = rem >> 9;
                int X = rem & 511;
                int y0, y1, x0, x1; float fy, fx;
                src_coord(Y, y0, y1, fy);
                src_coord(X, x0, x1, fx);
                const float4* base = (const float4*)(g_fT + ((size_t)b * SPIX) * DIM);
                float4 v00 = __ldg(base + (size_t)(y0 * WF + x0) * (DIM / 4) + d4);
                float4 v01 = __ldg(base + (size_t)(y0 * WF + x1) * (DIM / 4) + d4);
                float4 v10 = __ldg(base + (size_t)(y1 * WF + x0) * (DIM / 4) + d4);
                float4 v11 = __ldg(base + (size_t)(y1 * WF + x1) * (DIM / 4) + d4);
                float w00 = (1.f - fy) * (1.f - fx);
                float w01 = (1.f - fy) * fx;
                float w10 = fy * (1.f - fx);
                float w11 = fy * fx;
                acc.x += w * (w00 * v00.x + w01 * v01.x + w10 * v10.x + w11 * v11.x);
                acc.y += w * (w00 * v00.y + w01 * v01.y + w10 * v10.y + w11 * v11.y);
                acc.z += w * (w00 * v00.z + w01 * v01.z + w10 * v10.z + w11 * v11.z);
                acc.w += w * (w00 * v00.w + w01 * v01.w + w10 * v10.w + w11 * v11.w);
            }
        }
        sv[t] = acc;
        __syncthreads();
        if (sub < 2) {
            float4 a = sv[t], bq = sv[t + 128];
            a.x += bq.x; a.y += bq.y; a.z += bq.z; a.w += bq.w;
            sv[t] = a;
        }
        __syncthreads();
        if (sub == 0) {
            float4 a = sv[t], bq = sv[t + 64];
            a.x += bq.x; a.y += bq.y; a.z += bq.z; a.w += bq.w;
            ((float4*)g_part)[(c * GPARTS + p) * (DIM / 4) + d4] = a;
        }
        __threadfence();
        __syncthreads();
        if (t == 0) {
            s_last = (atomicAdd(&g_done[c], 1u) == GPARTS - 1u);
            unsigned gd = atomicAdd(&g_gdone, 1u);
            if (gd == (unsigned)(NC * GPARTS - 1)) {
                g_wtdone = 0u;          // all gates passed by everyone: safe to reset
                g_trdone = 0u;
                g_gdone  = 0u;
            }
        }
        __syncthreads();
        if (!s_last) return;

        // finalize (only last block of this class)
        __threadfence();
        int d = t;
        float tot = 0.f;
        #pragma unroll
        for (int q = 0; q < GPARTS; q++)
            tot += g_part[(c * GPARTS + q) * DIM + d];

        float wsum = g_wsum[c];
        float proto = tot / fmaxf(wsum, EPSV);

        red[d] = proto * proto;
        __syncthreads();
        for (int s = 128; s > 0; s >>= 1) {
            if (t < s) red[t] += red[t + s];
            __syncthreads();
        }
        float nrm = sqrtf(red[0]);
        __syncthreads();
        proto = proto / fmaxf(nrm, EPSV);

        bool has = g_has[c] != 0;
        float uc = update_count[c];
        float gamma = (uc == 0.f) ? 0.f : fminf(1.f - 1.f / (uc + 1.f), GAMMA_MAX);
        float oldp = prototypes[c * DIM + d];
        float nv = has ? (gamma * oldp + (1.f - gamma) * proto) : oldp;

        red[d] = nv * nv;
        __syncthreads();
        for (int s = 128; s > 0; s >>= 1) {
            if (t < s) red[t] += red[t + s];
            __syncthreads();
        }
        float nrm2 = sqrtf(red[0]);
        out[c * DIM + d] = nv / fmaxf(nrm2, EPSV);
        if (t == 0) {
            if (out_size >= NC * DIM + NC)
                out[NC * DIM + c] = uc + (has ? 1.f : 0.f);
            g_done[c]  = 0u;   // cleanup for next graph replay
            g_ready[c] = 0;
        }
    }
}

// ---------------- launch ----------------
extern "C" void kernel_launch(void* const* d_in, const int* in_sizes, int n_in,
                              void* d_out, int out_size) {
    const float* features     = (const float*)d_in[0];
    const float* weight       = (const float*)d_in[1];
    const float* prototypes   = (const float*)d_in[2];
    const float* update_count = (const float*)d_in[3];
    const int*   labels       = (const int*)d_in[4];
    float* out = (float*)d_out;

    k_all<<<ALL_BLOCKS, 256>>>(features, weight, labels,
                               prototypes, update_count, out, out_size);
}

// round 15
// speedup vs baseline: 1.3560x; 1.3560x over previous
#include <cuda_runtime.h>
#include <cuda_bf16.h>
#include <math.h>

#define BATCH 2
#define DIM   256
#define NC    19
#define TOPK  256
#define HF    128
#define WF    128
#define HH    512
#define WW    512
#define SPIX  (HF*WF)            // 16384
#define NPIX  (BATCH*HH*WW)      // 524288
#define EPSV  1e-12f
#define GAMMA_MAX 0.999f
#define NB    4096               // histogram bins over w in [0,1)
#define CCAP  1024               // candidate capacity (threshold bin)
#define GPARTS 8                 // gather blocks per class

// transpose tiling: 32 dims x 128 spatials per block
#define TR_STILES (SPIX / 128)   // 128
#define TR_DTILES (DIM / 32)     // 8
#define TR_BLOCKS (BATCH * TR_STILES * TR_DTILES)  // 2048
#define WT_BLOCKS (NPIX / 256)   // 2048 (1 pixel per thread)

// ---------------- scratch (static device memory; zero-init at load) ----------------
__device__ __align__(16) float g_fT[(size_t)BATCH*SPIX*DIM]; // features [B, HF*WF, DIM]
__device__ __align__(16) int2  g_li[(size_t)NC*NPIX];        // per-class (w_bits, idx) lists
__device__ __align__(16) int   g_hist[NC*NB];                // per-class global histograms
__device__ int   g_cnt[NC];                      // per-class list counts
__device__ float g_selw[NC*TOPK];                // selected weights
__device__ int   g_seli[NC*TOPK];                // selected pixel indices
__device__ float g_wsum[NC];                     // selected weight sums
__device__ int   g_has[NC];                      // class-present flags
__device__ __align__(16) float g_part[NC*GPARTS*DIM]; // gather partials
__device__ unsigned g_done[NC];                  // gather completion tickets

// ---------------- helpers ----------------
__device__ __forceinline__ void src_coord(int o, int &i0, int &i1, float &f) {
    float s = (o + 0.5f) * 0.25f - 0.5f;
    float fl = floorf(s);
    f = s - fl;
    int i = (int)fl;
    i0 = min(max(i, 0), HF - 1);
    i1 = min(max(i + 1, 0), HF - 1);
}

__device__ __forceinline__ int w_bin(float w) {
    int b = (int)(w * (float)NB);
    return min(NB - 1, max(0, b));
}

// ================= K1: fused reg-transpose (XOR swizzle) + weights (staged coalesced list) =================
__global__ void __launch_bounds__(256) k_main(const float* __restrict__ f,
                                              const float* __restrict__ weight,
                                              const int* __restrict__ labels) {
    if (blockIdx.x < TR_BLOCKS) {
        // ---- NCHW -> NHWC transpose: 4x4 register micro-transpose + swizzled smem ----
        __shared__ __align__(16) float4 tile4[128 * 8];   // 16 KB
        int i = blockIdx.x;
        int s0 = (i & (TR_STILES - 1)) * 128;
        int d0 = ((i / TR_STILES) & (TR_DTILES - 1)) * 32;
        int b  = i / (TR_STILES * TR_DTILES);
        int t  = threadIdx.x;

        int dq = t >> 5;              // 0..7 : 4-dim group
        int sq = t & 31;              // 0..31: 4-spatial group
        float4 v0 = __ldg((const float4*)(f + ((size_t)(b * DIM + d0 + 4 * dq + 0)) * SPIX + s0) + sq);
        float4 v1 = __ldg((const float4*)(f + ((size_t)(b * DIM + d0 + 4 * dq + 1)) * SPIX + s0) + sq);
        float4 v2 = __ldg((const float4*)(f + ((size_t)(b * DIM + d0 + 4 * dq + 2)) * SPIX + s0) + sq);
        float4 v3 = __ldg((const float4*)(f + ((size_t)(b * DIM + d0 + 4 * dq + 3)) * SPIX + s0) + sq);
        int col4 = dq ^ (sq & 7);
        tile4[(4 * sq + 0) * 8 + col4] = make_float4(v0.x, v1.x, v2.x, v3.x);
        tile4[(4 * sq + 1) * 8 + col4] = make_float4(v0.y, v1.y, v2.y, v3.y);
        tile4[(4 * sq + 2) * 8 + col4] = make_float4(v0.z, v1.z, v2.z, v3.z);
        tile4[(4 * sq + 3) * 8 + col4] = make_float4(v0.w, v1.w, v2.w, v3.w);
        __syncthreads();

        int d4 = t & 7;               // float4 dim group
        int sl = t >> 3;              // 0..31 spatial slot
        #pragma unroll
        for (int q = 0; q < 4; q++) {
            int s = sl + 32 * q;      // local spatial 0..127
            float4 v = tile4[s * 8 + (d4 ^ ((s >> 2) & 7))];
            *((float4*)(g_fT + ((size_t)(b * SPIX + s0 + s)) * DIM + d0) + d4) = v;
        }
    } else {
        // ---- per-pixel weight + histogram + CLASS-GROUPED COALESCED list append ----
        __shared__ int  s_cnt[NC];
        __shared__ int  s_pref[NC + 1];     // block-local class prefix
        __shared__ int  s_delta[NC];        // g_base[c] - s_pref[c]
        __shared__ int2 s_stage[256];
        int t = threadIdx.x;
        int n = (blockIdx.x - TR_BLOCKS) * 256 + t;
        if (t < NC) s_cnt[t] = 0;
        __syncthreads();

        int lab = labels[n];
        bool valid = ((unsigned)lab < NC);
        float w = 0.f;
        int r = 0;
        if (valid) {
            int b   = n >> 18;
            int rem = n & (HH * WW - 1);
            int Y = rem >> 9;
            int X = rem & 511;
            int y0, y1, x0, x1; float fy, fx;
            src_coord(Y, y0, y1, fy);
            src_coord(X, x0, x1, fx);
            const float* wp = weight + ((size_t)(b * NC + lab)) * SPIX;
            float v00 = __ldg(wp + y0 * WF + x0);
            float v01 = __ldg(wp + y0 * WF + x1);
            float v10 = __ldg(wp + y1 * WF + x0);
            float v11 = __ldg(wp + y1 * WF + x1);
            w = (1.f - fy) * ((1.f - fx) * v00 + fx * v01)
              +        fy  * ((1.f - fx) * v10 + fx * v11);
            r = atomicAdd(&s_cnt[lab], 1);
            atomicAdd(&g_hist[lab * NB + w_bin(w)], 1);
        }
        __syncthreads();
        if (t == 0) {
            int acc = 0;
            #pragma unroll
            for (int c = 0; c < NC; c++) { s_pref[c] = acc; acc += s_cnt[c]; }
            s_pref[NC] = acc;
        }
        __syncthreads();
        if (t < NC && s_cnt[t] > 0) {
            int gb = atomicAdd(&g_cnt[t], s_cnt[t]);
            s_delta[t] = gb - s_pref[t];
        }
        __syncthreads();
        if (valid)
            s_stage[s_pref[lab] + r] = make_int2(__float_as_int(w), n);
        __syncthreads();
        int total = s_pref[NC];
        if (t < total) {
            // class of slot t via binary search over s_pref (19 entries)
            int lo = 0, hi = NC - 1;
            while (lo < hi) {
                int mid = (lo + hi + 1) >> 1;
                if (s_pref[mid] <= t) lo = mid; else hi = mid - 1;
            }
            int2 v = s_stage[t];
            g_li[(size_t)lo * NPIX + (size_t)(t + s_delta[lo])] = v;
        }
    }
}

// ================= K2: per-class top-256 using precomputed histogram =================
__global__ void __launch_bounds__(1024) k_select() {
    int c = blockIdx.x;
    int t = threadIdx.x;
    int lane = t & 31, wid = t >> 5;

    __shared__ float s_w[TOPK];
    __shared__ int   s_i[TOPK];
    __shared__ float s_cw[CCAP];
    __shared__ int   s_ci[CCAP];
    __shared__ int   wsc[32];
    __shared__ float red[256];
    __shared__ int s_nsel, s_ncand, s_tb;

    int L = g_cnt[c];
    const int2* li = g_li + (size_t)c * NPIX;

    // load my 4 histogram bins (descending chunk order) + zero for next replay
    int4* hb = (int4*)(g_hist + c * NB);
    int rid = (NB / 4 - 1) - t;              // chunk t covers bins [4rid, 4rid+3]
    int4 hv = hb[rid];
    hb[rid] = make_int4(0, 0, 0, 0);

    if (t == 0) { s_nsel = 0; s_ncand = 0; s_tb = -1; }
    __syncthreads();

    if (L <= TOPK) {
        for (int i = t; i < TOPK; i += 1024) {
            if (i < L) { int2 e = li[i]; s_w[i] = __int_as_float(e.x); s_i[i] = e.y; }
            else       { s_w[i] = 0.f;   s_i[i] = 0; }
        }
        __syncthreads();
    } else {
        // ---- threshold bin from histogram (shuffle scan; bins descending) ----
        int chunk = hv.x + hv.y + hv.z + hv.w;
        int v = chunk;
        #pragma unroll
        for (int off = 1; off < 32; off <<= 1) {
            int nv = __shfl_up_sync(0xFFFFFFFFu, v, off);
            if (lane >= off) v += nv;
        }
        if (lane == 31) wsc[wid] = v;
        __syncthreads();
        if (wid == 0) {
            int ws = wsc[lane];
            int vv = ws;
            #pragma unroll
            for (int off = 1; off < 32; off <<= 1) {
                int nv = __shfl_up_sync(0xFFFFFFFFu, vv, off);
                if (lane >= off) vv += nv;
            }
            wsc[lane] = vv - ws;       // exclusive warp offset
        }
        __syncthreads();
        int P_incl = v + wsc[wid];
        int P_excl = P_incl - chunk;
        if (P_incl >= TOPK && P_excl < TOPK) {
            int acc = P_excl;
            int cnts[4] = {hv.x, hv.y, hv.z, hv.w};
            #pragma unroll
            for (int k = 3; k >= 0; k--) {
                int h = cnts[k];
                if (acc + h >= TOPK) { s_tb = 4 * rid + k; break; }
                acc += h;
            }
        }
        __syncthreads();
        int tb = s_tb;

        // ---- single list pass: partition into selected / candidates (int4 = 2 entries) ----
        int L2e = L & ~1;
        for (int i = t * 2; i < L2e; i += 2048) {
            int4 q = *(const int4*)(li + i);
            float wq[2] = {__int_as_float(q.x), __int_as_float(q.z)};
            int   iq[2] = {q.y, q.w};
            #pragma unroll
            for (int j = 0; j < 2; j++) {
                int bin = w_bin(wq[j]);
                if (bin > tb) {
                    int p = atomicAdd(&s_nsel, 1);
                    s_w[p] = wq[j]; s_i[p] = iq[j];
                } else if (bin == tb) {
                    int q2 = atomicAdd(&s_ncand, 1);
                    if (q2 < CCAP) { s_cw[q2] = wq[j]; s_ci[q2] = iq[j]; }
                }
            }
        }
        if (L2e < L && t == 0) {
            int2 e = li[L2e];
            float w = __int_as_float(e.x);
            int bin = w_bin(w);
            if (bin > tb) {
                int p = atomicAdd(&s_nsel, 1);
                s_w[p] = w; s_i[p] = e.y;
            } else if (bin == tb) {
                int q2 = atomicAdd(&s_ncand, 1);
                if (q2 < CCAP) { s_cw[q2] = w; s_ci[q2] = e.y; }
            }
        }
        __syncthreads();

        // ---- parallel rank select from threshold bin ----
        int above = s_nsel;
        int r = TOPK - above;
        int L2 = min(s_ncand, CCAP);
        if (r > 0) {
            for (int i = t; i < L2; i += 1024) {
                float wi = s_cw[i];
                int rank = 0;
                for (int j = 0; j < L2; j++) {
                    float wj = s_cw[j];
                    rank += (wj > wi) || (wj == wi && j < i);
                }
                if (rank < r) { s_w[above + rank] = wi; s_i[above + rank] = s_ci[i]; }
            }
        }
        int nsel = above + ((r > 0) ? min(r, L2) : 0);
        __syncthreads();
        for (int i = t; i < TOPK; i += 1024)
            if (i >= nsel) { s_w[i] = 0.f; s_i[i] = 0; }
        __syncthreads();
    }

    // ---- weight sum + publish selection ----
    if (t < TOPK) {
        red[t] = s_w[t];
        g_selw[c * TOPK + t] = s_w[t];
        g_seli[c * TOPK + t] = s_i[t];
    }
    __syncthreads();
    if (t < 128) red[t] += red[t + 128];
    __syncthreads();
    if (t < 64) red[t] += red[t + 64];
    __syncthreads();
    if (t < 32) {
        float v = red[t] + red[t + 32];
        #pragma unroll
        for (int off = 16; off > 0; off >>= 1)
            v += __shfl_down_sync(0xFFFFFFFFu, v, off);
        if (t == 0) {
            g_wsum[c] = v;
            g_has[c]  = (L > 0) && (v > 0.f);
            g_cnt[c]  = 0;             // cleanup for next graph replay
        }
    }
}

// ================= K3: gather partials + last-block finalize =================
__global__ void __launch_bounds__(256) k_gather(
        const float* __restrict__ prototypes,
        const float* __restrict__ update_count,
        float* __restrict__ out, int out_size) {
    int c = blockIdx.x >> 3;           // class
    int p = blockIdx.x & (GPARTS - 1); // part: 32 pixels
    int t = threadIdx.x;
    int d4  = t & 63;                  // float4 dim group
    int sub = t >> 6;                  // 0..3, 8 pixels each

    __shared__ float4 sv[256];
    __shared__ float red[256];
    __shared__ int s_last;

    float4 acc = make_float4(0.f, 0.f, 0.f, 0.f);
    int k0 = p * 32 + sub * 8;
    #pragma unroll
    for (int k = k0; k < k0 + 8; k++) {
        float w = g_selw[c * TOPK + k];
        if (w > 0.f) {
            int n   = g_seli[c * TOPK + k];
            int b   = n >> 18;
            int rem = n & (HH * WW - 1);
            int Y = rem >> 9;
            int X = rem & 511;
            int y0, y1, x0, x1; float fy, fx;
            src_coord(Y, y0, y1, fy);
            src_coord(X, x0, x1, fx);
            const float4* base = (const float4*)(g_fT + ((size_t)b * SPIX) * DIM);
            float4 v00 = __ldg(base + (size_t)(y0 * WF + x0) * (DIM / 4) + d4);
            float4 v01 = __ldg(base + (size_t)(y0 * WF + x1) * (DIM / 4) + d4);
            float4 v10 = __ldg(base + (size_t)(y1 * WF + x0) * (DIM / 4) + d4);
            float4 v11 = __ldg(base + (size_t)(y1 * WF + x1) * (DIM / 4) + d4);
            float w00 = (1.f - fy) * (1.f - fx);
            float w01 = (1.f - fy) * fx;
            float w10 = fy * (1.f - fx);
            float w11 = fy * fx;
            acc.x += w * (w00 * v00.x + w01 * v01.x + w10 * v10.x + w11 * v11.x);
            acc.y += w * (w00 * v00.y + w01 * v01.y + w10 * v10.y + w11 * v11.y);
            acc.z += w * (w00 * v00.z + w01 * v01.z + w10 * v10.z + w11 * v11.z);
            acc.w += w * (w00 * v00.w + w01 * v01.w + w10 * v10.w + w11 * v11.w);
        }
    }
    sv[t] = acc;
    __syncthreads();
    if (sub < 2) {
        float4 a = sv[t], bq = sv[t + 128];
        a.x += bq.x; a.y += bq.y; a.z += bq.z; a.w += bq.w;
        sv[t] = a;
    }
    __syncthreads();
    if (sub == 0) {
        float4 a = sv[t], bq = sv[t + 64];
        a.x += bq.x; a.y += bq.y; a.z += bq.z; a.w += bq.w;
        ((float4*)g_part)[(c * GPARTS + p) * (DIM / 4) + d4] = a;
    }
    __threadfence();
    __syncthreads();
    if (t == 0)
        s_last = (atomicAdd(&g_done[c], 1u) == GPARTS - 1u);
    __syncthreads();
    if (!s_last) return;

    // finalize (only last block of this class)
    __threadfence();
    int d = t;
    float tot = 0.f;
    #pragma unroll
    for (int q = 0; q < GPARTS; q++)
        tot += g_part[(c * GPARTS + q) * DIM + d];

    float wsum = g_wsum[c];
    float proto = tot / fmaxf(wsum, EPSV);

    red[d] = proto * proto;
    __syncthreads();
    for (int s = 128; s > 0; s >>= 1) {
        if (t < s) red[t] += red[t + s];
        __syncthreads();
    }
    float nrm = sqrtf(red[0]);
    __syncthreads();
    proto = proto / fmaxf(nrm, EPSV);

    bool has = g_has[c] != 0;
    float uc = update_count[c];
    float gamma = (uc == 0.f) ? 0.f : fminf(1.f - 1.f / (uc + 1.f), GAMMA_MAX);
    float oldp = prototypes[c * DIM + d];
    float nv = has ? (gamma * oldp + (1.f - gamma) * proto) : oldp;

    red[d] = nv * nv;
    __syncthreads();
    for (int s = 128; s > 0; s >>= 1) {
        if (t < s) red[t] += red[t + s];
        __syncthreads();
    }
    float nrm2 = sqrtf(red[0]);
    out[c * DIM + d] = nv / fmaxf(nrm2, EPSV);
    if (t == 0) {
        if (out_size >= NC * DIM + NC)
            out[NC * DIM + c] = uc + (has ? 1.f : 0.f);
        g_done[c] = 0u;   // cleanup for next graph replay
    }
}

// ---------------- launch ----------------
extern "C" void kernel_launch(void* const* d_in, const int* in_sizes, int n_in,
                              void* d_out, int out_size) {
    const float* features     = (const float*)d_in[0];
    const float* weight       = (const float*)d_in[1];
    const float* prototypes   = (const float*)d_in[2];
    const float* update_count = (const float*)d_in[3];
    const int*   labels       = (const int*)d_in[4];
    float* out = (float*)d_out;

    k_main<<<TR_BLOCKS + WT_BLOCKS, 256>>>(features, weight, labels);
    k_select<<<NC, 1024>>>();
    k_gather<<<NC * GPARTS, 256>>>(prototypes, update_count, out, out_size);
}

// round 16
// speedup vs baseline: 1.5544x; 1.1463x over previous
#include <cuda_runtime.h>
#include <cuda_bf16.h>
#include <cuda_fp16.h>
#include <math.h>

#define BATCH 2
#define DIM   256
#define NC    19
#define TOPK  256
#define HF    128
#define WF    128
#define HH    512
#define WW    512
#define SPIX  (HF*WF)            // 16384
#define NPIX  (BATCH*HH*WW)      // 524288
#define EPSV  1e-12f
#define GAMMA_MAX 0.999f
#define NB    4096               // histogram bins over w in [0,1)
#define CCAP  1024               // candidate capacity (threshold bin)
#define GPARTS 8                 // gather blocks per class

// transpose tiling: 32 dims x 128 spatials per block
#define TR_STILES (SPIX / 128)   // 128
#define TR_DTILES (DIM / 32)     // 8
#define TR_BLOCKS (BATCH * TR_STILES * TR_DTILES)  // 2048
#define WT_BLOCKS (NPIX / 256)   // 2048 (1 pixel per thread)

// ---------------- scratch (static device memory; zero-init at load) ----------------
__device__ __align__(16) __half g_fT[(size_t)BATCH*SPIX*DIM]; // features fp16 [B, HF*WF, DIM]
__device__ __align__(16) float g_cw[(size_t)NC*NPIX];        // per-class weight lists
__device__ __align__(16) int   g_cidx[(size_t)NC*NPIX];      // per-class pixel-index lists
__device__ __align__(16) int   g_hist[NC*NB];                // per-class global histograms
__device__ int   g_cnt[NC];                      // per-class list counts
__device__ float g_selw[NC*TOPK];                // selected weights
__device__ int   g_seli[NC*TOPK];                // selected pixel indices
__device__ float g_wsum[NC];                     // selected weight sums
__device__ int   g_has[NC];                      // class-present flags
__device__ __align__(16) float g_part[NC*GPARTS*DIM]; // gather partials
__device__ unsigned g_done[NC];                  // gather completion tickets

// ---------------- helpers ----------------
__device__ __forceinline__ void src_coord(int o, int &i0, int &i1, float &f) {
    float s = (o + 0.5f) * 0.25f - 0.5f;
    float fl = floorf(s);
    f = s - fl;
    int i = (int)fl;
    i0 = min(max(i, 0), HF - 1);
    i1 = min(max(i + 1, 0), HF - 1);
}

__device__ __forceinline__ int w_bin(float w) {
    int b = (int)(w * (float)NB);
    return min(NB - 1, max(0, b));
}

__device__ __forceinline__ float4 h4_to_f4(uint2 r) {
    __half2 a = *reinterpret_cast<__half2*>(&r.x);
    __half2 b = *reinterpret_cast<__half2*>(&r.y);
    float2 fa = __half22float2(a);
    float2 fb = __half22float2(b);
    return make_float4(fa.x, fa.y, fb.x, fb.y);
}

// ================= K1: fused reg-transpose (XOR swizzle, fp16 out) + weights/list/hist =================
__global__ void __launch_bounds__(256) k_main(const float* __restrict__ f,
                                              const float* __restrict__ weight,
                                              const int* __restrict__ labels) {
    if (blockIdx.x < TR_BLOCKS) {
        // ---- NCHW -> NHWC transpose: 4x4 register micro-transpose + swizzled smem ----
        __shared__ __align__(16) float4 tile4[128 * 8];   // 16 KB
        int i = blockIdx.x;
        int s0 = (i & (TR_STILES - 1)) * 128;
        int d0 = ((i / TR_STILES) & (TR_DTILES - 1)) * 32;
        int b  = i / (TR_STILES * TR_DTILES);
        int t  = threadIdx.x;

        int dq = t >> 5;              // 0..7 : 4-dim group
        int sq = t & 31;              // 0..31: 4-spatial group
        float4 v0 = __ldg((const float4*)(f + ((size_t)(b * DIM + d0 + 4 * dq + 0)) * SPIX + s0) + sq);
        float4 v1 = __ldg((const float4*)(f + ((size_t)(b * DIM + d0 + 4 * dq + 1)) * SPIX + s0) + sq);
        float4 v2 = __ldg((const float4*)(f + ((size_t)(b * DIM + d0 + 4 * dq + 2)) * SPIX + s0) + sq);
        float4 v3 = __ldg((const float4*)(f + ((size_t)(b * DIM + d0 + 4 * dq + 3)) * SPIX + s0) + sq);
        int col4 = dq ^ (sq & 7);
        tile4[(4 * sq + 0) * 8 + col4] = make_float4(v0.x, v1.x, v2.x, v3.x);
        tile4[(4 * sq + 1) * 8 + col4] = make_float4(v0.y, v1.y, v2.y, v3.y);
        tile4[(4 * sq + 2) * 8 + col4] = make_float4(v0.z, v1.z, v2.z, v3.z);
        tile4[(4 * sq + 3) * 8 + col4] = make_float4(v0.w, v1.w, v2.w, v3.w);
        __syncthreads();

        int d4 = t & 7;               // 4-dim group (as uint2 of 4 halves)
        int sl = t >> 3;              // 0..31 spatial slot
        #pragma unroll
        for (int q = 0; q < 4; q++) {
            int s = sl + 32 * q;      // local spatial 0..127
            float4 v = tile4[s * 8 + (d4 ^ ((s >> 2) & 7))];
            __half2 h0 = __floats2half2_rn(v.x, v.y);
            __half2 h1 = __floats2half2_rn(v.z, v.w);
            uint2 r;
            r.x = *reinterpret_cast<unsigned*>(&h0);
            r.y = *reinterpret_cast<unsigned*>(&h1);
            *((uint2*)(g_fT + ((size_t)(b * SPIX + s0 + s)) * DIM + d0) + d4) = r;
        }
    } else {
        // ---- per-pixel weight + per-class list append + global histogram ----
        __shared__ int s_cnt[NC];
        __shared__ int s_base[NC];
        int n = (blockIdx.x - TR_BLOCKS) * 256 + threadIdx.x;
        if (threadIdx.x < NC) s_cnt[threadIdx.x] = 0;
        __syncthreads();

        int lab = labels[n];
        bool valid = ((unsigned)lab < NC);
        float w = 0.f;
        int r = 0;
        if (valid) {
            int b   = n >> 18;
            int rem = n & (HH * WW - 1);
            int Y = rem >> 9;
            int X = rem & 511;
            int y0, y1, x0, x1; float fy, fx;
            src_coord(Y, y0, y1, fy);
            src_coord(X, x0, x1, fx);
            const float* wp = weight + ((size_t)(b * NC + lab)) * SPIX;
            float v00 = __ldg(wp + y0 * WF + x0);
            float v01 = __ldg(wp + y0 * WF + x1);
            float v10 = __ldg(wp + y1 * WF + x0);
            float v11 = __ldg(wp + y1 * WF + x1);
            w = (1.f - fy) * ((1.f - fx) * v00 + fx * v01)
              +        fy  * ((1.f - fx) * v10 + fx * v11);
            r = atomicAdd(&s_cnt[lab], 1);
            atomicAdd(&g_hist[lab * NB + w_bin(w)], 1);   // no return use -> RED
        }
        __syncthreads();
        if (threadIdx.x < NC && s_cnt[threadIdx.x] > 0)
            s_base[threadIdx.x] = atomicAdd(&g_cnt[threadIdx.x], s_cnt[threadIdx.x]);
        __syncthreads();
        if (valid) {
            size_t o = (size_t)lab * NPIX + (size_t)(s_base[lab] + r);
            g_cw[o]   = w;
            g_cidx[o] = n;
        }
    }
}

// ================= K2: per-class top-256 using precomputed histogram =================
__global__ void __launch_bounds__(1024) k_select() {
    int c = blockIdx.x;
    int t = threadIdx.x;
    int lane = t & 31, wid = t >> 5;

    __shared__ float s_w[TOPK];
    __shared__ int   s_i[TOPK];
    __shared__ float s_cw[CCAP];
    __shared__ int   s_ci[CCAP];
    __shared__ int   wsc[32];
    __shared__ float red[256];
    __shared__ int s_nsel, s_ncand, s_tb;

    int L = g_cnt[c];
    const float* cw = g_cw   + (size_t)c * NPIX;
    const int*   ci = g_cidx + (size_t)c * NPIX;

    // load my 4 histogram bins (descending chunk order) + zero for next replay
    int4* hb = (int4*)(g_hist + c * NB);
    int rid = (NB / 4 - 1) - t;              // chunk t covers bins [4rid, 4rid+3]
    int4 hv = hb[rid];
    hb[rid] = make_int4(0, 0, 0, 0);

    if (t == 0) { s_nsel = 0; s_ncand = 0; s_tb = -1; }
    __syncthreads();

    if (L <= TOPK) {
        for (int i = t; i < TOPK; i += 1024) {
            if (i < L) { s_w[i] = cw[i]; s_i[i] = ci[i]; }
            else       { s_w[i] = 0.f;   s_i[i] = 0; }
        }
        __syncthreads();
    } else {
        // ---- threshold bin from histogram (shuffle scan; bins descending) ----
        int chunk = hv.x + hv.y + hv.z + hv.w;
        int v = chunk;
        #pragma unroll
        for (int off = 1; off < 32; off <<= 1) {
            int nv = __shfl_up_sync(0xFFFFFFFFu, v, off);
            if (lane >= off) v += nv;
        }
        if (lane == 31) wsc[wid] = v;
        __syncthreads();
        if (wid == 0) {
            int ws = wsc[lane];
            int vv = ws;
            #pragma unroll
            for (int off = 1; off < 32; off <<= 1) {
                int nv = __shfl_up_sync(0xFFFFFFFFu, vv, off);
                if (lane >= off) vv += nv;
            }
            wsc[lane] = vv - ws;       // exclusive warp offset
        }
        __syncthreads();
        int P_incl = v + wsc[wid];
        int P_excl = P_incl - chunk;
        if (P_incl >= TOPK && P_excl < TOPK) {
            int acc = P_excl;
            int cnts[4] = {hv.x, hv.y, hv.z, hv.w};
            #pragma unroll
            for (int k = 3; k >= 0; k--) {
                int h = cnts[k];
                if (acc + h >= TOPK) { s_tb = 4 * rid + k; break; }
                acc += h;
            }
        }
        __syncthreads();
        int tb = s_tb;

        // ---- single list pass: partition into selected / candidates ----
        int L4 = L & ~3;
        for (int i = t * 4; i < L4; i += 4096) {
            float4 vq = *(const float4*)(cw + i);
            int4   xq = *(const int4*)(ci + i);
            float wq[4] = {vq.x, vq.y, vq.z, vq.w};
            int   iq[4] = {xq.x, xq.y, xq.z, xq.w};
            #pragma unroll
            for (int j = 0; j < 4; j++) {
                int bin = w_bin(wq[j]);
                if (bin > tb) {
                    int p = atomicAdd(&s_nsel, 1);
                    s_w[p] = wq[j]; s_i[p] = iq[j];
                } else if (bin == tb) {
                    int q = atomicAdd(&s_ncand, 1);
                    if (q < CCAP) { s_cw[q] = wq[j]; s_ci[q] = iq[j]; }
                }
            }
        }
        for (int i = L4 + t; i < L; i += 1024) {
            float w = cw[i];
            int bin = w_bin(w);
            if (bin > tb) {
                int p = atomicAdd(&s_nsel, 1);
                s_w[p] = w; s_i[p] = ci[i];
            } else if (bin == tb) {
                int q = atomicAdd(&s_ncand, 1);
                if (q < CCAP) { s_cw[q] = w; s_ci[q] = ci[i]; }
            }
        }
        __syncthreads();

        // ---- parallel rank select from threshold bin ----
        int above = s_nsel;
        int r = TOPK - above;
        int L2 = min(s_ncand, CCAP);
        if (r > 0) {
            for (int i = t; i < L2; i += 1024) {
                float wi = s_cw[i];
                int rank = 0;
                for (int j = 0; j < L2; j++) {
                    float wj = s_cw[j];
                    rank += (wj > wi) || (wj == wi && j < i);
                }
                if (rank < r) { s_w[above + rank] = wi; s_i[above + rank] = s_ci[i]; }
            }
        }
        int nsel = above + ((r > 0) ? min(r, L2) : 0);
        __syncthreads();
        for (int i = t; i < TOPK; i += 1024)
            if (i >= nsel) { s_w[i] = 0.f; s_i[i] = 0; }
        __syncthreads();
    }

    // ---- weight sum + publish selection ----
    if (t < TOPK) {
        red[t] = s_w[t];
        g_selw[c * TOPK + t] = s_w[t];
        g_seli[c * TOPK + t] = s_i[t];
    }
    __syncthreads();
    if (t < 128) red[t] += red[t + 128];
    __syncthreads();
    if (t < 64) red[t] += red[t + 64];
    __syncthreads();
    if (t < 32) {
        float v = red[t] + red[t + 32];
        #pragma unroll
        for (int off = 16; off > 0; off >>= 1)
            v += __shfl_down_sync(0xFFFFFFFFu, v, off);
        if (t == 0) {
            g_wsum[c] = v;
            g_has[c]  = (L > 0) && (v > 0.f);
            g_cnt[c]  = 0;             // cleanup for next graph replay
        }
    }
}

// ================= K3: gather partials (fp16 features) + last-block finalize =================
__global__ void __launch_bounds__(256) k_gather(
        const float* __restrict__ prototypes,
        const float* __restrict__ update_count,
        float* __restrict__ out, int out_size) {
    int c = blockIdx.x >> 3;           // class
    int p = blockIdx.x & (GPARTS - 1); // part: 32 pixels
    int t = threadIdx.x;
    int d4  = t & 63;                  // 4-dim group (uint2 of 4 halves)
    int sub = t >> 6;                  // 0..3, 8 pixels each

    __shared__ float4 sv[256];
    __shared__ float red[256];
    __shared__ int s_last;

    float4 acc = make_float4(0.f, 0.f, 0.f, 0.f);
    int k0 = p * 32 + sub * 8;
    #pragma unroll
    for (int k = k0; k < k0 + 8; k++) {
        float w = g_selw[c * TOPK + k];
        if (w > 0.f) {
            int n   = g_seli[c * TOPK + k];
            int b   = n >> 18;
            int rem = n & (HH * WW - 1);
            int Y = rem >> 9;
            int X = rem & 511;
            int y0, y1, x0, x1; float fy, fx;
            src_coord(Y, y0, y1, fy);
            src_coord(X, x0, x1, fx);
            const uint2* base = (const uint2*)(g_fT + ((size_t)b * SPIX) * DIM);
            float4 v00 = h4_to_f4(__ldg(base + (size_t)(y0 * WF + x0) * (DIM / 4) + d4));
            float4 v01 = h4_to_f4(__ldg(base + (size_t)(y0 * WF + x1) * (DIM / 4) + d4));
            float4 v10 = h4_to_f4(__ldg(base + (size_t)(y1 * WF + x0) * (DIM / 4) + d4));
            float4 v11 = h4_to_f4(__ldg(base + (size_t)(y1 * WF + x1) * (DIM / 4) + d4));
            float w00 = (1.f - fy) * (1.f - fx);
            float w01 = (1.f - fy) * fx;
            float w10 = fy * (1.f - fx);
            float w11 = fy * fx;
            acc.x += w * (w00 * v00.x + w01 * v01.x + w10 * v10.x + w11 * v11.x);
            acc.y += w * (w00 * v00.y + w01 * v01.y + w10 * v10.y + w11 * v11.y);
            acc.z += w * (w00 * v00.z + w01 * v01.z + w10 * v10.z + w11 * v11.z);
            acc.w += w * (w00 * v00.w + w01 * v01.w + w10 * v10.w + w11 * v11.w);
        }
    }
    sv[t] = acc;
    __syncthreads();
    if (sub < 2) {
        float4 a = sv[t], bq = sv[t + 128];
        a.x += bq.x; a.y += bq.y; a.z += bq.z; a.w += bq.w;
        sv[t] = a;
    }
    __syncthreads();
    if (sub == 0) {
        float4 a = sv[t], bq = sv[t + 64];
        a.x += bq.x; a.y += bq.y; a.z += bq.z; a.w += bq.w;
        ((float4*)g_part)[(c * GPARTS + p) * (DIM / 4) + d4] = a;
    }
    __threadfence();
    __syncthreads();
    if (t == 0)
        s_last = (atomicAdd(&g_done[c], 1u) == GPARTS - 1u);
    __syncthreads();
    if (!s_last) return;

    // finalize (only last block of this class)
    __threadfence();
    int d = t;
    float tot = 0.f;
    #pragma unroll
    for (int q = 0; q < GPARTS; q++)
        tot += g_part[(c * GPARTS + q) * DIM + d];

    float wsum = g_wsum[c];
    float proto = tot / fmaxf(wsum, EPSV);

    red[d] = proto * proto;
    __syncthreads();
    for (int s = 128; s > 0; s >>= 1) {
        if (t < s) red[t] += red[t + s];
        __syncthreads();
    }
    float nrm = sqrtf(red[0]);
    __syncthreads();
    proto = proto / fmaxf(nrm, EPSV);

    bool has = g_has[c] != 0;
    float uc = update_count[c];
    float gamma = (uc == 0.f) ? 0.f : fminf(1.f - 1.f / (uc + 1.f), GAMMA_MAX);
    float oldp = prototypes[c * DIM + d];
    float nv = has ? (gamma * oldp + (1.f - gamma) * proto) : oldp;

    red[d] = nv * nv;
    __syncthreads();
    for (int s = 128; s > 0; s >>= 1) {
        if (t < s) red[t] += red[t + s];
        __syncthreads();
    }
    float nrm2 = sqrtf(red[0]);
    out[c * DIM + d] = nv / fmaxf(nrm2, EPSV);
    if (t == 0) {
        if (out_size >= NC * DIM + NC)
            out[NC * DIM + c] = uc + (has ? 1.f : 0.f);
        g_done[c] = 0u;   // cleanup for next graph replay
    }
}

// ---------------- launch ----------------
extern "C" void kernel_launch(void* const* d_in, const int* in_sizes, int n_in,
                              void* d_out, int out_size) {
    const float* features     = (const float*)d_in[0];
    const float* weight       = (const float*)d_in[1];
    const float* prototypes   = (const float*)d_in[2];
    const float* update_count = (const float*)d_in[3];
    const int*   labels       = (const int*)d_in[4];
    float* out = (float*)d_out;

    k_main<<<TR_BLOCKS + WT_BLOCKS, 256>>>(features, weight, labels);
    k_select<<<NC, 1024>>>();
    k_gather<<<NC * GPARTS, 256>>>(prototypes, update_count, out, out_size);
}